// round 8
// baseline (speedup 1.0000x reference)
#include <cuda_runtime.h>
#include <stdint.h>

#define N_NODES 50000
#define M_PIV   2048
#define D_DIM   256
#define P_DIM   8
#define K_DIM   (P_DIM * D_DIM)   // 2048

#define QSCALE 67108864.0   // 2^26

// Scratch (device globals: allocation-free per harness rules)
__device__ int g_A[(size_t)N_NODES * K_DIM];  // ~410 MB
__device__ int g_B[(size_t)M_PIV * K_DIM];    // ~16 MB

// ---------------------------------------------------------------------------
// Prep: v = src[row,d]*W[p,d] (fp32); norm accumulated EXACTLY in fp64,
// rounded once to fp32; divide in fp32 (identical numerics to the passing
// round-2 kernel). Then quantize: q = round(vn * 2^26) -> int32 (|vn|<=1).
// ---------------------------------------------------------------------------
__global__ void __launch_bounds__(256) prep_kernel(const float* __restrict__ src,
                                                   const float* __restrict__ W,
                                                   int* __restrict__ dst) {
    int row = blockIdx.x;
    int d   = threadIdx.x;
    float x = src[(size_t)row * D_DIM + d];

    __shared__ double red[8];
    __shared__ float s_norm;

    for (int p = 0; p < P_DIM; p++) {
        float v = x * W[p * D_DIM + d];
        double s = (double)v * (double)v;  // exact product
        #pragma unroll
        for (int o = 16; o > 0; o >>= 1)
            s += __shfl_xor_sync(0xffffffffu, s, o);
        if ((d & 31) == 0) red[d >> 5] = s;
        __syncthreads();
        if (d == 0) {
            double t = 0.0;
            #pragma unroll
            for (int w = 0; w < 8; w++) t += red[w];
            float n = (float)sqrt(t);          // correctly-rounded fp32 norm
            s_norm = fmaxf(n, 1e-12f);
        }
        __syncthreads();
        float vn = v / s_norm;                 // |vn| <= 1
        dst[(size_t)row * K_DIM + p * D_DIM + d] =
            (int)__double2ll_rn((double)vn * QSCALE);
        __syncthreads();  // protect red/s_norm for next p
    }
}

// ---------------------------------------------------------------------------
// GEMM, exact int64 accumulation of int32 products (IMAD.WIDE):
// C[n,m] = fl32( 0.125 * 2^-52 * sum_k qA[n,k]*qB[m,k] )
// 128x64 block tile, BK=16, 8x4 per thread, 256 threads.
// ---------------------------------------------------------------------------
#define BM 128
#define BN 64
#define BK 16

__global__ void __launch_bounds__(256, 2) gemm_kernel(const int* __restrict__ A,
                                                      const int* __restrict__ B,
                                                      float* __restrict__ C) {
    __shared__ int As[BK][BM + 4];
    __shared__ int Bs[BK][BN + 4];

    const int bm  = blockIdx.y * BM;
    const int bn  = blockIdx.x * BN;
    const int tid = threadIdx.x;
    const int tx  = tid & 15;   // col group (16 x 4 = 64)
    const int ty  = tid >> 4;   // row group (16 x 8 = 128)

    long long acc[8][4];
    #pragma unroll
    for (int i = 0; i < 8; i++)
        #pragma unroll
        for (int j = 0; j < 4; j++) acc[i][j] = 0ll;

    for (int k0 = 0; k0 < K_DIM; k0 += BK) {
        // A tile: 128 rows x 16 k = 512 int4 units, 2 per thread
        #pragma unroll
        for (int j = 0; j < 2; j++) {
            int u = tid + 256 * j;
            int r = u >> 2;              // 0..127
            int kp = (u & 3) * 4;        // 0,4,8,12
            int grow = bm + r;
            int4 val;
            if (grow < N_NODES)
                val = *(const int4*)&A[(size_t)grow * K_DIM + k0 + kp];
            else
                val = make_int4(0, 0, 0, 0);
            As[kp + 0][r] = val.x; As[kp + 1][r] = val.y;
            As[kp + 2][r] = val.z; As[kp + 3][r] = val.w;
        }
        // B tile: 64 rows x 16 k = 256 int4 units, 1 per thread
        {
            int r = tid >> 2;
            int kp = (tid & 3) * 4;
            int4 val = *(const int4*)&B[(size_t)(bn + r) * K_DIM + k0 + kp];
            Bs[kp + 0][r] = val.x; Bs[kp + 1][r] = val.y;
            Bs[kp + 2][r] = val.z; Bs[kp + 3][r] = val.w;
        }
        __syncthreads();

        #pragma unroll
        for (int kk = 0; kk < BK; kk++) {
            int af[8], bf[4];
            #pragma unroll
            for (int i = 0; i < 8; i++) af[i] = As[kk][ty * 8 + i];
            #pragma unroll
            for (int j = 0; j < 4; j++) bf[j] = Bs[kk][tx * 4 + j];
            #pragma unroll
            for (int i = 0; i < 8; i++)
                #pragma unroll
                for (int j = 0; j < 4; j++)
                    acc[i][j] += (long long)af[i] * bf[j];   // IMAD.WIDE
        }
        __syncthreads();
    }

    const double SCALE = 0.125 / (QSCALE * QSCALE);  // 2^-55
    #pragma unroll
    for (int i = 0; i < 8; i++) {
        int grow = bm + ty * 8 + i;
        if (grow < N_NODES) {
            #pragma unroll
            for (int j = 0; j < 4; j++)
                C[(size_t)grow * M_PIV + bn + tx * 4 + j] =
                    (float)((double)acc[i][j] * SCALE);
        }
    }
}

// ---------------------------------------------------------------------------
// Top-k in place: keep the k largest per row (ties -> lowest index, matching
// jax.lax.top_k), zero the rest. One block per row, k sequential argmax passes.
// ---------------------------------------------------------------------------
__global__ void __launch_bounds__(256) topk_kernel(float* __restrict__ out,
                                                   const int* __restrict__ topk_ptr) {
    int row = blockIdx.x;
    float* rowp = out + (size_t)row * M_PIV;

    __shared__ float vals[M_PIV];
    __shared__ float orig[M_PIV];
    __shared__ unsigned char keep[M_PIV];
    __shared__ unsigned long long warp_best[8];
    const int tid = threadIdx.x;

    for (int i = tid; i < M_PIV; i += 256) {
        float v = rowp[i];
        vals[i] = v;
        orig[i] = v;
        keep[i] = 0;
    }
    __syncthreads();

    int k = *topk_ptr;
    if (k > M_PIV) k = M_PIV;

    for (int it = 0; it < k; it++) {
        unsigned long long best = 0ull;
        for (int i = tid; i < M_PIV; i += 256) {
            unsigned u = __float_as_uint(vals[i]);
            u = (u & 0x80000000u) ? ~u : (u | 0x80000000u);  // orderable float
            unsigned long long key =
                ((unsigned long long)u << 32) | (unsigned)(M_PIV - 1 - i);
            if (key > best) best = key;
        }
        #pragma unroll
        for (int o = 16; o > 0; o >>= 1) {
            unsigned long long other = __shfl_xor_sync(0xffffffffu, best, o);
            if (other > best) best = other;
        }
        if ((tid & 31) == 0) warp_best[tid >> 5] = best;
        __syncthreads();
        if (tid < 32) {
            unsigned long long b = (tid < 8) ? warp_best[tid] : 0ull;
            #pragma unroll
            for (int o = 4; o > 0; o >>= 1) {
                unsigned long long other = __shfl_xor_sync(0xffffffffu, b, o);
                if (other > b) b = other;
            }
            if (tid == 0) {
                int idx = M_PIV - 1 - (int)(b & 0xffffffffu);
                keep[idx] = 1;
                vals[idx] = __int_as_float(0xff800000);  // -inf: exclude
            }
        }
        __syncthreads();
    }

    for (int i = tid; i < M_PIV; i += 256)
        rowp[i] = keep[i] ? orig[i] : 0.0f;
}

// ---------------------------------------------------------------------------
extern "C" void kernel_launch(void* const* d_in, const int* in_sizes, int n_in,
                              void* d_out, int out_size) {
    const float* nodes  = (const float*)d_in[0];  // [50000, 256]
    const float* pivots = (const float*)d_in[1];  // [2048, 256]
    const float* W      = (const float*)d_in[2];  // [8, 256]
    const int*   topk   = (const int*)d_in[3];    // scalar
    float* out = (float*)d_out;                   // [50000, 2048]

    int *dA = nullptr, *dB = nullptr;
    cudaGetSymbolAddress((void**)&dA, g_A);
    cudaGetSymbolAddress((void**)&dB, g_B);

    prep_kernel<<<N_NODES, 256>>>(nodes, W, dA);
    prep_kernel<<<M_PIV, 256>>>(pivots, W, dB);

    dim3 grid(M_PIV / BN, (N_NODES + BM - 1) / BM);  // (32, 391)
    gemm_kernel<<<grid, 256>>>(dA, dB, out);

    topk_kernel<<<N_NODES, 256>>>(out, topk);
}

// round 9
// speedup vs baseline: 1.0003x; 1.0003x over previous
#include <cuda_runtime.h>
#include <stdint.h>

#define N_NODES 50000
#define M_PIV   2048
#define D_DIM   256
#define P_DIM   8
#define K_DIM   (P_DIM * D_DIM)   // 2048

#define QSCALE 67108864.0   // 2^26

// Scratch (device globals: allocation-free per harness rules)
__device__ int g_A[(size_t)N_NODES * K_DIM];  // ~410 MB
__device__ int g_B[(size_t)M_PIV * K_DIM];    // ~16 MB

// ---------------------------------------------------------------------------
// Prep: v = src[row,d]*W[p,d] (fp32); norm accumulated EXACTLY in fp64,
// rounded once to fp32; divide in fp32 (identical numerics to the passing
// round-2 kernel). Then quantize: q = round(vn * 2^26) -> int32 (|vn|<=1).
// ---------------------------------------------------------------------------
__global__ void __launch_bounds__(256) prep_kernel(const float* __restrict__ src,
                                                   const float* __restrict__ W,
                                                   int* __restrict__ dst) {
    int row = blockIdx.x;
    int d   = threadIdx.x;
    float x = src[(size_t)row * D_DIM + d];

    __shared__ double red[8];
    __shared__ float s_norm;

    for (int p = 0; p < P_DIM; p++) {
        float v = x * W[p * D_DIM + d];
        double s = (double)v * (double)v;  // exact product
        #pragma unroll
        for (int o = 16; o > 0; o >>= 1)
            s += __shfl_xor_sync(0xffffffffu, s, o);
        if ((d & 31) == 0) red[d >> 5] = s;
        __syncthreads();
        if (d == 0) {
            double t = 0.0;
            #pragma unroll
            for (int w = 0; w < 8; w++) t += red[w];
            float n = (float)sqrt(t);          // correctly-rounded fp32 norm
            s_norm = fmaxf(n, 1e-12f);
        }
        __syncthreads();
        float vn = v / s_norm;                 // |vn| <= 1
        dst[(size_t)row * K_DIM + p * D_DIM + d] =
            (int)__double2ll_rn((double)vn * QSCALE);
        __syncthreads();  // protect red/s_norm for next p
    }
}

// ---------------------------------------------------------------------------
// GEMM, exact int64 accumulation of int32 products (IMAD.WIDE):
// C[n,m] = fl32( 0.125 * 2^-52 * sum_k qA[n,k]*qB[m,k] )
// 128x64 block tile, BK=16, 8x4 per thread, 256 threads.
// ---------------------------------------------------------------------------
#define BM 128
#define BN 64
#define BK 16

__global__ void __launch_bounds__(256, 2) gemm_kernel(const int* __restrict__ A,
                                                      const int* __restrict__ B,
                                                      float* __restrict__ C) {
    __shared__ int As[BK][BM + 4];
    __shared__ int Bs[BK][BN + 4];

    const int bm  = blockIdx.y * BM;
    const int bn  = blockIdx.x * BN;
    const int tid = threadIdx.x;
    const int tx  = tid & 15;   // col group (16 x 4 = 64)
    const int ty  = tid >> 4;   // row group (16 x 8 = 128)

    long long acc[8][4];
    #pragma unroll
    for (int i = 0; i < 8; i++)
        #pragma unroll
        for (int j = 0; j < 4; j++) acc[i][j] = 0ll;

    for (int k0 = 0; k0 < K_DIM; k0 += BK) {
        // A tile: 128 rows x 16 k = 512 int4 units, 2 per thread
        #pragma unroll
        for (int j = 0; j < 2; j++) {
            int u = tid + 256 * j;
            int r = u >> 2;              // 0..127
            int kp = (u & 3) * 4;        // 0,4,8,12
            int grow = bm + r;
            int4 val;
            if (grow < N_NODES)
                val = *(const int4*)&A[(size_t)grow * K_DIM + k0 + kp];
            else
                val = make_int4(0, 0, 0, 0);
            As[kp + 0][r] = val.x; As[kp + 1][r] = val.y;
            As[kp + 2][r] = val.z; As[kp + 3][r] = val.w;
        }
        // B tile: 64 rows x 16 k = 256 int4 units, 1 per thread
        {
            int r = tid >> 2;
            int kp = (tid & 3) * 4;
            int4 val = *(const int4*)&B[(size_t)(bn + r) * K_DIM + k0 + kp];
            Bs[kp + 0][r] = val.x; Bs[kp + 1][r] = val.y;
            Bs[kp + 2][r] = val.z; Bs[kp + 3][r] = val.w;
        }
        __syncthreads();

        #pragma unroll
        for (int kk = 0; kk < BK; kk++) {
            int af[8], bf[4];
            #pragma unroll
            for (int i = 0; i < 8; i++) af[i] = As[kk][ty * 8 + i];
            #pragma unroll
            for (int j = 0; j < 4; j++) bf[j] = Bs[kk][tx * 4 + j];
            #pragma unroll
            for (int i = 0; i < 8; i++)
                #pragma unroll
                for (int j = 0; j < 4; j++)
                    acc[i][j] += (long long)af[i] * bf[j];   // IMAD.WIDE
        }
        __syncthreads();
    }

    const double SCALE = 0.125 / (QSCALE * QSCALE);  // 2^-55
    #pragma unroll
    for (int i = 0; i < 8; i++) {
        int grow = bm + ty * 8 + i;
        if (grow < N_NODES) {
            #pragma unroll
            for (int j = 0; j < 4; j++)
                C[(size_t)grow * M_PIV + bn + tx * 4 + j] =
                    (float)((double)acc[i][j] * SCALE);
        }
    }
}

// ---------------------------------------------------------------------------
// Top-k in place: keep the k largest per row (ties -> lowest index, matching
// jax.lax.top_k), zero the rest. One block per row, k sequential argmax passes.
// ---------------------------------------------------------------------------
__global__ void __launch_bounds__(256) topk_kernel(float* __restrict__ out,
                                                   const int* __restrict__ topk_ptr) {
    int row = blockIdx.x;
    float* rowp = out + (size_t)row * M_PIV;

    __shared__ float vals[M_PIV];
    __shared__ float orig[M_PIV];
    __shared__ unsigned char keep[M_PIV];
    __shared__ unsigned long long warp_best[8];
    const int tid = threadIdx.x;

    for (int i = tid; i < M_PIV; i += 256) {
        float v = rowp[i];
        vals[i] = v;
        orig[i] = v;
        keep[i] = 0;
    }
    __syncthreads();

    int k = *topk_ptr;
    if (k > M_PIV) k = M_PIV;

    for (int it = 0; it < k; it++) {
        unsigned long long best = 0ull;
        for (int i = tid; i < M_PIV; i += 256) {
            unsigned u = __float_as_uint(vals[i]);
            u = (u & 0x80000000u) ? ~u : (u | 0x80000000u);  // orderable float
            unsigned long long key =
                ((unsigned long long)u << 32) | (unsigned)(M_PIV - 1 - i);
            if (key > best) best = key;
        }
        #pragma unroll
        for (int o = 16; o > 0; o >>= 1) {
            unsigned long long other = __shfl_xor_sync(0xffffffffu, best, o);
            if (other > best) best = other;
        }
        if ((tid & 31) == 0) warp_best[tid >> 5] = best;
        __syncthreads();
        if (tid < 32) {
            unsigned long long b = (tid < 8) ? warp_best[tid] : 0ull;
            #pragma unroll
            for (int o = 4; o > 0; o >>= 1) {
                unsigned long long other = __shfl_xor_sync(0xffffffffu, b, o);
                if (other > b) b = other;
            }
            if (tid == 0) {
                int idx = M_PIV - 1 - (int)(b & 0xffffffffu);
                keep[idx] = 1;
                vals[idx] = __int_as_float(0xff800000);  // -inf: exclude
            }
        }
        __syncthreads();
    }

    for (int i = tid; i < M_PIV; i += 256)
        rowp[i] = keep[i] ? orig[i] : 0.0f;
}

// ---------------------------------------------------------------------------
extern "C" void kernel_launch(void* const* d_in, const int* in_sizes, int n_in,
                              void* d_out, int out_size) {
    const float* nodes  = (const float*)d_in[0];  // [50000, 256]
    const float* pivots = (const float*)d_in[1];  // [2048, 256]
    const float* W      = (const float*)d_in[2];  // [8, 256]
    const int*   topk   = (const int*)d_in[3];    // scalar
    float* out = (float*)d_out;                   // [50000, 2048]

    int *dA = nullptr, *dB = nullptr;
    cudaGetSymbolAddress((void**)&dA, g_A);
    cudaGetSymbolAddress((void**)&dB, g_B);

    prep_kernel<<<N_NODES, 256>>>(nodes, W, dA);
    prep_kernel<<<M_PIV, 256>>>(pivots, W, dB);

    dim3 grid(M_PIV / BN, (N_NODES + BM - 1) / BM);  // (32, 391)
    gemm_kernel<<<grid, 256>>>(dA, dB, out);

    topk_kernel<<<N_NODES, 256>>>(out, topk);
}

// round 10
// speedup vs baseline: 1.0009x; 1.0005x over previous
#include <cuda_runtime.h>
#include <stdint.h>

#define N_NODES 50000
#define M_PIV   2048
#define D_DIM   256
#define P_DIM   8
#define K_DIM   (P_DIM * D_DIM)   // 2048

#define QSCALE 67108864.0   // 2^26

// Scratch (device globals: allocation-free per harness rules)
__device__ int g_A[(size_t)N_NODES * K_DIM];  // ~410 MB
__device__ int g_B[(size_t)M_PIV * K_DIM];    // ~16 MB

// ---------------------------------------------------------------------------
// Prep: v = src[row,d]*W[p,d] (fp32); norm accumulated EXACTLY in fp64,
// rounded once to fp32; divide in fp32 (identical numerics to the passing
// round-2 kernel). Then quantize: q = round(vn * 2^26) -> int32 (|vn|<=1).
// ---------------------------------------------------------------------------
__global__ void __launch_bounds__(256) prep_kernel(const float* __restrict__ src,
                                                   const float* __restrict__ W,
                                                   int* __restrict__ dst) {
    int row = blockIdx.x;
    int d   = threadIdx.x;
    float x = src[(size_t)row * D_DIM + d];

    __shared__ double red[8];
    __shared__ float s_norm;

    for (int p = 0; p < P_DIM; p++) {
        float v = x * W[p * D_DIM + d];
        double s = (double)v * (double)v;  // exact product
        #pragma unroll
        for (int o = 16; o > 0; o >>= 1)
            s += __shfl_xor_sync(0xffffffffu, s, o);
        if ((d & 31) == 0) red[d >> 5] = s;
        __syncthreads();
        if (d == 0) {
            double t = 0.0;
            #pragma unroll
            for (int w = 0; w < 8; w++) t += red[w];
            float n = (float)sqrt(t);          // correctly-rounded fp32 norm
            s_norm = fmaxf(n, 1e-12f);
        }
        __syncthreads();
        float vn = v / s_norm;                 // |vn| <= 1
        dst[(size_t)row * K_DIM + p * D_DIM + d] =
            (int)__double2ll_rn((double)vn * QSCALE);
        __syncthreads();  // protect red/s_norm for next p
    }
}

// ---------------------------------------------------------------------------
// GEMM, exact int64 accumulation of int32 products (IMAD.WIDE):
// C[n,m] = fl32( 0.125 * 2^-52 * sum_k qA[n,k]*qB[m,k] )
// 128x64 block tile, BK=16, 8x4 per thread, 256 threads.
// ---------------------------------------------------------------------------
#define BM 128
#define BN 64
#define BK 16

__global__ void __launch_bounds__(256, 2) gemm_kernel(const int* __restrict__ A,
                                                      const int* __restrict__ B,
                                                      float* __restrict__ C) {
    __shared__ int As[BK][BM + 4];
    __shared__ int Bs[BK][BN + 4];

    const int bm  = blockIdx.y * BM;
    const int bn  = blockIdx.x * BN;
    const int tid = threadIdx.x;
    const int tx  = tid & 15;   // col group (16 x 4 = 64)
    const int ty  = tid >> 4;   // row group (16 x 8 = 128)

    long long acc[8][4];
    #pragma unroll
    for (int i = 0; i < 8; i++)
        #pragma unroll
        for (int j = 0; j < 4; j++) acc[i][j] = 0ll;

    for (int k0 = 0; k0 < K_DIM; k0 += BK) {
        // A tile: 128 rows x 16 k = 512 int4 units, 2 per thread
        #pragma unroll
        for (int j = 0; j < 2; j++) {
            int u = tid + 256 * j;
            int r = u >> 2;              // 0..127
            int kp = (u & 3) * 4;        // 0,4,8,12
            int grow = bm + r;
            int4 val;
            if (grow < N_NODES)
                val = *(const int4*)&A[(size_t)grow * K_DIM + k0 + kp];
            else
                val = make_int4(0, 0, 0, 0);
            As[kp + 0][r] = val.x; As[kp + 1][r] = val.y;
            As[kp + 2][r] = val.z; As[kp + 3][r] = val.w;
        }
        // B tile: 64 rows x 16 k = 256 int4 units, 1 per thread
        {
            int r = tid >> 2;
            int kp = (tid & 3) * 4;
            int4 val = *(const int4*)&B[(size_t)(bn + r) * K_DIM + k0 + kp];
            Bs[kp + 0][r] = val.x; Bs[kp + 1][r] = val.y;
            Bs[kp + 2][r] = val.z; Bs[kp + 3][r] = val.w;
        }
        __syncthreads();

        #pragma unroll
        for (int kk = 0; kk < BK; kk++) {
            int af[8], bf[4];
            #pragma unroll
            for (int i = 0; i < 8; i++) af[i] = As[kk][ty * 8 + i];
            #pragma unroll
            for (int j = 0; j < 4; j++) bf[j] = Bs[kk][tx * 4 + j];
            #pragma unroll
            for (int i = 0; i < 8; i++)
                #pragma unroll
                for (int j = 0; j < 4; j++)
                    acc[i][j] += (long long)af[i] * bf[j];   // IMAD.WIDE
        }
        __syncthreads();
    }

    const double SCALE = 0.125 / (QSCALE * QSCALE);  // 2^-55
    #pragma unroll
    for (int i = 0; i < 8; i++) {
        int grow = bm + ty * 8 + i;
        if (grow < N_NODES) {
            #pragma unroll
            for (int j = 0; j < 4; j++)
                C[(size_t)grow * M_PIV + bn + tx * 4 + j] =
                    (float)((double)acc[i][j] * SCALE);
        }
    }
}

// ---------------------------------------------------------------------------
// Top-k in place: keep the k largest per row (ties -> lowest index, matching
// jax.lax.top_k), zero the rest. One block per row, k sequential argmax passes.
// ---------------------------------------------------------------------------
__global__ void __launch_bounds__(256) topk_kernel(float* __restrict__ out,
                                                   const int* __restrict__ topk_ptr) {
    int row = blockIdx.x;
    float* rowp = out + (size_t)row * M_PIV;

    __shared__ float vals[M_PIV];
    __shared__ float orig[M_PIV];
    __shared__ unsigned char keep[M_PIV];
    __shared__ unsigned long long warp_best[8];
    const int tid = threadIdx.x;

    for (int i = tid; i < M_PIV; i += 256) {
        float v = rowp[i];
        vals[i] = v;
        orig[i] = v;
        keep[i] = 0;
    }
    __syncthreads();

    int k = *topk_ptr;
    if (k > M_PIV) k = M_PIV;

    for (int it = 0; it < k; it++) {
        unsigned long long best = 0ull;
        for (int i = tid; i < M_PIV; i += 256) {
            unsigned u = __float_as_uint(vals[i]);
            u = (u & 0x80000000u) ? ~u : (u | 0x80000000u);  // orderable float
            unsigned long long key =
                ((unsigned long long)u << 32) | (unsigned)(M_PIV - 1 - i);
            if (key > best) best = key;
        }
        #pragma unroll
        for (int o = 16; o > 0; o >>= 1) {
            unsigned long long other = __shfl_xor_sync(0xffffffffu, best, o);
            if (other > best) best = other;
        }
        if ((tid & 31) == 0) warp_best[tid >> 5] = best;
        __syncthreads();
        if (tid < 32) {
            unsigned long long b = (tid < 8) ? warp_best[tid] : 0ull;
            #pragma unroll
            for (int o = 4; o > 0; o >>= 1) {
                unsigned long long other = __shfl_xor_sync(0xffffffffu, b, o);
                if (other > b) b = other;
            }
            if (tid == 0) {
                int idx = M_PIV - 1 - (int)(b & 0xffffffffu);
                keep[idx] = 1;
                vals[idx] = __int_as_float(0xff800000);  // -inf: exclude
            }
        }
        __syncthreads();
    }

    for (int i = tid; i < M_PIV; i += 256)
        rowp[i] = keep[i] ? orig[i] : 0.0f;
}

// ---------------------------------------------------------------------------
extern "C" void kernel_launch(void* const* d_in, const int* in_sizes, int n_in,
                              void* d_out, int out_size) {
    const float* nodes  = (const float*)d_in[0];  // [50000, 256]
    const float* pivots = (const float*)d_in[1];  // [2048, 256]
    const float* W      = (const float*)d_in[2];  // [8, 256]
    const int*   topk   = (const int*)d_in[3];    // scalar
    float* out = (float*)d_out;                   // [50000, 2048]

    int *dA = nullptr, *dB = nullptr;
    cudaGetSymbolAddress((void**)&dA, g_A);
    cudaGetSymbolAddress((void**)&dB, g_B);

    prep_kernel<<<N_NODES, 256>>>(nodes, W, dA);
    prep_kernel<<<M_PIV, 256>>>(pivots, W, dB);

    dim3 grid(M_PIV / BN, (N_NODES + BM - 1) / BM);  // (32, 391)
    gemm_kernel<<<grid, 256>>>(dA, dB, out);

    topk_kernel<<<N_NODES, 256>>>(out, topk);
}